// round 1
// baseline (speedup 1.0000x reference)
#include <cuda_runtime.h>

// out[b,h,w] = depth[k1]/NORM where k1 = first k in [0,106] with a "valid sign change":
//   signs s[k] = sgn(ssp[k+1]-ssp[k]), k=0..105
//   change at k: k==0 -> s[0]<0 ; 1<=k<=105 -> s[k]<s[k-1] ; k==106 -> s[105]>0
//   killed if pattern [1,0,1] matches at (k-1,k,k+1)   (valid 1<=k<=104)
//        or if pattern [1,-1,0,0] matches at (k-1..k+2) (valid 1<=k<=103)
//   depth[k] = depth_array[k], except k==0 contributes 0.

static __device__ __forceinline__ int sgnf(float d) {
    return (int)(d > 0.0f) - (int)(d < 0.0f);
}

struct Scan {
    int h0, h1, h2, h3;  // s[j], s[j-1], s[j-2], s[j-3]
    int k;
    bool done;
};

// Consume sign s[jj]; finalizes the decision for index k = jj-2 (needs s[k+2] lookahead),
// and handles k==0 immediately at jj==0 (patterns can't apply at k==0).
static __device__ __forceinline__ void step(Scan& s, int sj, int jj) {
    s.h3 = s.h2; s.h2 = s.h1; s.h1 = s.h0; s.h0 = sj;
    if (!s.done) {
        if (jj == 0) {
            if (sj < 0) { s.done = true; s.k = 0; }
        } else if (jj >= 3) {
            // decide k = jj-2: s[k-1]=h3, s[k]=h2, s[k+1]=h1, s[k+2]=h0
            bool change = s.h2 < s.h3;
            bool p1 = (s.h3 == 1) & (s.h2 == 0)  & (s.h1 == 1);
            bool p2 = (s.h3 == 1) & (s.h2 == -1) & (s.h1 == 0) & (s.h0 == 0);
            if (change & (!p1) & (!p2)) { s.done = true; s.k = jj - 2; }
        }
    }
}

__global__ void __launch_bounds__(256) ecs_kernel(
    const float* __restrict__ ssp,
    const float* __restrict__ depth_arr,
    float* __restrict__ out,
    int total)
{
    const int HW = 65536;  // 256*256
    int idx = blockIdx.x * blockDim.x + threadIdx.x;
    bool valid = (idx < total);
    int cidx = valid ? idx : (total - 1);
    const float* p = ssp + (long)(cidx >> 16) * (107L * HW) + (cidx & (HW - 1));

    Scan st; st.h0 = st.h1 = st.h2 = st.h3 = 9; st.k = 0; st.done = !valid;

    float x0 = __ldg(p);  // x[0]
    int j = 0;
    // 26 chunks of 4 signs: j = 0..103 (decisions k = 0..101)
    #pragma unroll 1
    for (int c = 0; c < 26; ++c) {
        if (!st.done) {
            float x1 = __ldg(p + (j + 1) * HW);
            float x2 = __ldg(p + (j + 2) * HW);
            float x3 = __ldg(p + (j + 3) * HW);
            float x4 = __ldg(p + (j + 4) * HW);
            step(st, sgnf(x1 - x0), j);
            step(st, sgnf(x2 - x1), j + 1);
            step(st, sgnf(x3 - x2), j + 2);
            step(st, sgnf(x4 - x3), j + 3);
            x0 = x4;
        }
        j += 4;
        if (__all_sync(0xffffffffu, st.done)) break;
    }

    if (!st.done) {
        // loop ran to completion for this warp: x0 == x[104], history = s[100..103]
        float x105 = __ldg(p + 105 * HW);
        float x106 = __ldg(p + 106 * HW);
        step(st, sgnf(x105 - x0), 104);    // decides k=102
        step(st, sgnf(x106 - x105), 105);  // decides k=103
        if (!st.done) {
            // h0=s[105], h1=s[104], h2=s[103]
            bool chg104 = st.h1 < st.h2;
            bool p1_104 = (st.h2 == 1) & (st.h1 == 0) & (st.h0 == 1);  // pattern1 valid up to k=104
            if (chg104 & (!p1_104))  { st.done = true; st.k = 104; }
            else if (st.h0 < st.h1)  { st.done = true; st.k = 105; }   // no patterns at k=105
            else if (st.h0 > 0)      { st.done = true; st.k = 106; }   // boundary: -s[105] < 0
        }
    }

    if (valid) {
        float val = 0.0f;
        if (st.done && st.k > 0)
            val = __ldg(depth_arr + st.k) / 670.25141631f;
        out[idx] = val;
    }
}

extern "C" void kernel_launch(void* const* d_in, const int* in_sizes, int n_in,
                              void* d_out, int out_size) {
    const float* ssp   = (const float*)d_in[0];
    const float* depth = (const float*)d_in[1];
    float* out = (float*)d_out;
    int total = out_size;  // 8*256*256 = 524288
    int block = 256;
    int grid = (total + block - 1) / block;
    ecs_kernel<<<grid, block>>>(ssp, depth, out, total);
}

// round 2
// speedup vs baseline: 1.1500x; 1.1500x over previous
#include <cuda_runtime.h>

// out[b,h,w] = depth[k1]/NORM where k1 = first k in [0,106] with a "valid sign change":
//   signs s[k] = sgn(ssp[k+1]-ssp[k]), k=0..105
//   change at k: k==0 -> s[0]<0 ; 1<=k<=105 -> s[k]<s[k-1] ; k==106 -> s[105]>0
//   killed if pattern [1,0,1] matches at (k-1,k,k+1)   (valid 1<=k<=104)
//        or if pattern [1,-1,0,0] matches at (k-1..k+2) (valid 1<=k<=103)
//   depth[k] = depth_array[k], except k==0 contributes 0.

static __device__ __forceinline__ int sgnf(float d) {
    return (int)(d > 0.0f) - (int)(d < 0.0f);
}

struct Scan {
    int h0, h1, h2, h3;  // s[j], s[j-1], s[j-2], s[j-3]
    int k;
    bool done;
};

// Consume sign s[jj]; finalizes the decision for index k = jj-2 (needs s[k+2] lookahead),
// and handles k==0 immediately at jj==0 (patterns can't apply at k==0).
static __device__ __forceinline__ void step(Scan& s, int sj, int jj) {
    s.h3 = s.h2; s.h2 = s.h1; s.h1 = s.h0; s.h0 = sj;
    if (!s.done) {
        if (jj == 0) {
            if (sj < 0) { s.done = true; s.k = 0; }
        } else if (jj >= 3) {
            // decide k = jj-2: s[k-1]=h3, s[k]=h2, s[k+1]=h1, s[k+2]=h0
            bool change = s.h2 < s.h3;
            bool p1 = (s.h3 == 1) & (s.h2 == 0)  & (s.h1 == 1);
            bool p2 = (s.h3 == 1) & (s.h2 == -1) & (s.h1 == 0) & (s.h0 == 0);
            if (change & (!p1) & (!p2)) { s.done = true; s.k = jj - 2; }
        }
    }
}

__global__ void __launch_bounds__(256) ecs_kernel(
    const float* __restrict__ ssp,
    const float* __restrict__ depth_arr,
    float* __restrict__ out,
    int total)
{
    const int HW = 65536;  // 256*256
    const int HEAD = 13;   // slices loaded up-front: signs 0..11, decisions k<=9
    int idx = blockIdx.x * blockDim.x + threadIdx.x;
    bool valid = (idx < total);
    int cidx = valid ? idx : (total - 1);
    const float* p = ssp + (long)(cidx >> 16) * (107L * HW) + (cidx & (HW - 1));

    Scan st; st.h0 = st.h1 = st.h2 = st.h3 = 9; st.k = 0; st.done = !valid;

    // ---- Head: one big batched round trip, MLP=13 ----
    float x[HEAD];
    #pragma unroll
    for (int i = 0; i < HEAD; ++i) x[i] = __ldg(p + i * HW);
    #pragma unroll
    for (int i = 0; i < HEAD - 1; ++i) step(st, sgnf(x[i + 1] - x[i]), i);
    float x0 = x[HEAD - 1];  // x[12]

    // ---- Rare tail (~0.4% of warps): chunks of 4 signs, j = 12..103 ----
    if (!__all_sync(0xffffffffu, st.done)) {
        int j = HEAD - 1;  // next sign index = 12
        #pragma unroll 1
        for (int c = 0; c < 23; ++c) {
            if (!st.done) {
                float x1 = __ldg(p + (j + 1) * HW);
                float x2 = __ldg(p + (j + 2) * HW);
                float x3 = __ldg(p + (j + 3) * HW);
                float x4 = __ldg(p + (j + 4) * HW);
                step(st, sgnf(x1 - x0), j);
                step(st, sgnf(x2 - x1), j + 1);
                step(st, sgnf(x3 - x2), j + 2);
                step(st, sgnf(x4 - x3), j + 3);
                x0 = x4;
            }
            j += 4;
            if (__all_sync(0xffffffffu, st.done)) break;
        }

        if (!st.done) {
            // loop ran to completion: x0 == x[104], history = s[100..103]
            float x105 = __ldg(p + 105 * HW);
            float x106 = __ldg(p + 106 * HW);
            step(st, sgnf(x105 - x0), 104);    // decides k=102
            step(st, sgnf(x106 - x105), 105);  // decides k=103
            if (!st.done) {
                // h0=s[105], h1=s[104], h2=s[103]
                bool chg104 = st.h1 < st.h2;
                bool p1_104 = (st.h2 == 1) & (st.h1 == 0) & (st.h0 == 1);
                if (chg104 & (!p1_104))  { st.done = true; st.k = 104; }
                else if (st.h0 < st.h1)  { st.done = true; st.k = 105; }
                else if (st.h0 > 0)      { st.done = true; st.k = 106; }
            }
        }
    }

    if (valid) {
        float val = 0.0f;
        if (st.done && st.k > 0)
            val = __ldg(depth_arr + st.k) / 670.25141631f;
        out[idx] = val;
    }
}

extern "C" void kernel_launch(void* const* d_in, const int* in_sizes, int n_in,
                              void* d_out, int out_size) {
    const float* ssp   = (const float*)d_in[0];
    const float* depth = (const float*)d_in[1];
    float* out = (float*)d_out;
    int total = out_size;  // 8*256*256 = 524288
    int block = 256;
    int grid = (total + block - 1) / block;
    ecs_kernel<<<grid, block>>>(ssp, depth, out, total);
}

// round 3
// speedup vs baseline: 1.1882x; 1.0332x over previous
#include <cuda_runtime.h>

// out[col] = depth[k1]/NORM, k1 = first k in [0,106] with a valid sign change.
//   signs s[k] = sgn(ssp[k+1]-ssp[k]), k=0..105
//   change: k==0 -> s[0]<0 ; 1<=k<=105 -> s[k]<s[k-1] ; k==106 -> s[105]>0
//   killed if [1,0,1] at (k-1,k,k+1) (k<=104) or [1,-1,0,0] at (k-1..k+2) (k<=103)
//   depth[0] contributes 0.

static __device__ __forceinline__ int sgn_cmp(float a, float b) {
    return (int)(b > a) - (int)(b < a);  // sign of (b - a), FTZ-immune
}

struct Scan { int h0, h1, h2, h3; int k; bool done; };

// Tail step (only used for sign index jj >= 12): decides k = jj-2.
static __device__ __forceinline__ void step_t(Scan& s, int sj, int jj) {
    s.h3 = s.h2; s.h2 = s.h1; s.h1 = s.h0; s.h0 = sj;
    if (!s.done) {
        bool change = s.h2 < s.h3;
        bool p1 = (s.h3 == 1) & (s.h2 == 0)  & (s.h1 == 1);
        bool p2 = (s.h3 == 1) & (s.h2 == -1) & (s.h1 == 0) & (s.h0 == 0);
        if (change & (!p1) & (!p2)) { s.done = true; s.k = jj - 2; }
    }
}

// Rare tail: scan signs 12..105 (+ boundary k=106). x0 = x[12], history = s[8..11].
static __device__ __noinline__ int tail_scan(const float* __restrict__ p, float x0,
                                             int s8, int s9, int s10, int s11) {
    const int HW = 65536;
    Scan st; st.h3 = s8; st.h2 = s9; st.h1 = s10; st.h0 = s11; st.k = 0; st.done = false;
    int j = 12;
    #pragma unroll 1
    for (int c = 0; c < 23; ++c) {   // signs 12..103, decisions k = 10..101
        float x1 = __ldg(p + (j + 1) * HW);
        float x2 = __ldg(p + (j + 2) * HW);
        float x3 = __ldg(p + (j + 3) * HW);
        float x4 = __ldg(p + (j + 4) * HW);
        step_t(st, sgn_cmp(x0, x1), j);
        step_t(st, sgn_cmp(x1, x2), j + 1);
        step_t(st, sgn_cmp(x2, x3), j + 2);
        step_t(st, sgn_cmp(x3, x4), j + 3);
        x0 = x4;
        j += 4;
        if (st.done) return st.k;
    }
    // here x0 = x[104], history = s[100..103]
    float x105 = __ldg(p + 105 * HW);
    float x106 = __ldg(p + 106 * HW);
    step_t(st, sgn_cmp(x0, x105), 104);     // decides k=102
    step_t(st, sgn_cmp(x105, x106), 105);   // decides k=103
    if (!st.done) {
        // h0=s[105], h1=s[104], h2=s[103]
        bool chg104 = st.h1 < st.h2;
        bool p1_104 = (st.h2 == 1) & (st.h1 == 0) & (st.h0 == 1);
        if (chg104 & (!p1_104))  st.k = 104;
        else if (st.h0 < st.h1)  st.k = 105;   // no patterns possible at k=105
        else if (st.h0 > 0)      st.k = 106;   // boundary: -s[105] < 0
        else                     st.k = 0;     // no change anywhere
    }
    return st.k;
}

// Head decision for one column from 13 depth samples: returns k in [0,9], or -1 (undecided).
static __device__ __forceinline__ int head_decide(const float x[13], unsigned& P, unsigned& N) {
    unsigned p = 0, n = 0;
    #pragma unroll
    for (int i = 0; i < 12; ++i) {
        p |= ((unsigned)(x[i + 1] > x[i])) << i;
        n |= ((unsigned)(x[i + 1] < x[i])) << i;
    }
    P = p; N = n;
    unsigned Z  = ~(p | n) & 0xFFFu;
    unsigned C  = ((p << 1) & ~p) | ((Z << 1) & n);          // change at k (k>=1)
    unsigned P1 = (p << 1) & Z & (p >> 1);                   // [1,0,1]
    unsigned P2 = (p << 1) & n & (Z >> 1) & (Z >> 2);        // [1,-1,0,0]
    unsigned vmask = ((C & ~(P1 | P2)) | (n & 1u)) & 0x3FFu; // decisions k=0..9 only
    return vmask ? (__ffs(vmask) - 1) : -1;
}

static __device__ __forceinline__ int sbit(unsigned P, unsigned N, int i) {
    return (int)((P >> i) & 1u) - (int)((N >> i) & 1u);
}

__global__ void __launch_bounds__(256) ecs_kernel(
    const float* __restrict__ ssp,
    const float* __restrict__ depth_arr,
    float* __restrict__ out)
{
    const int HW = 65536;  // 256*256
    int t = blockIdx.x * 256 + threadIdx.x;   // 0..262143, 2 columns per thread
    int col0 = t * 2;
    const float* p = ssp + (long)(col0 >> 16) * (107L * HW) + (col0 & (HW - 1));
    const float2* p2 = reinterpret_cast<const float2*>(p);

    // One batched round trip: 13 x LDG.64 (MLP=13)
    float xa[13], xb[13];
    #pragma unroll
    for (int i = 0; i < 13; ++i) {
        float2 v = __ldg(p2 + i * (HW / 2));
        xa[i] = v.x; xb[i] = v.y;
    }

    unsigned Pa, Na, Pb, Nb;
    int ka = head_decide(xa, Pa, Na);
    int kb = head_decide(xb, Pb, Nb);

    if (ka < 0)
        ka = tail_scan(p, xa[12], sbit(Pa, Na, 8), sbit(Pa, Na, 9),
                       sbit(Pa, Na, 10), sbit(Pa, Na, 11));
    if (kb < 0)
        kb = tail_scan(p + 1, xb[12], sbit(Pb, Nb, 8), sbit(Pb, Nb, 9),
                       sbit(Pb, Nb, 10), sbit(Pb, Nb, 11));

    const float NORM = 670.25141631f;
    float2 res;
    res.x = (ka > 0) ? __ldg(depth_arr + ka) / NORM : 0.0f;
    res.y = (kb > 0) ? __ldg(depth_arr + kb) / NORM : 0.0f;
    reinterpret_cast<float2*>(out)[t] = res;
}

extern "C" void kernel_launch(void* const* d_in, const int* in_sizes, int n_in,
                              void* d_out, int out_size) {
    const float* ssp   = (const float*)d_in[0];
    const float* depth = (const float*)d_in[1];
    float* out = (float*)d_out;
    // out_size = 524288 exactly; 2 columns/thread, 256 threads/block -> 1024 blocks
    int blocks = out_size / 512;
    ecs_kernel<<<blocks, 256>>>(ssp, depth, out);
}